// round 8
// baseline (speedup 1.0000x reference)
#include <cuda_runtime.h>
#include <cuda_bf16.h>

#define N_PTS 10000
#define DIM 64
#define EPS 0.4f
#define BM 128
#define NB ((N_PTS + BM - 1) / BM)       // 79
#define NTRI (NB * (NB + 1) / 2)          // 3160 upper-triangle blocks
#define ECAP (1 << 22)                    // 4M edge capacity (expect ~27K)
#define SM_EDGES 32768                    // edges cached in cc smem
#define WORDS ((N_PTS + 31) / 32)         // 313

// -------- static device scratch (no allocations allowed) --------
__device__ float g_nf_T[DIM * N_PTS];  // normalized features, TRANSPOSED [d][p]
__device__ int   g_ecount;             // edge counter
__device__ int2  g_edges[ECAP];        // edge list (u < v)

// -------- packed f32x2 helpers (sm_100a: FFMA2 = 2x FMA throughput) --------
__device__ __forceinline__ void unpack2(unsigned long long p, float& lo, float& hi) {
    asm("mov.b64 {%0, %1}, %2;" : "=f"(lo), "=f"(hi) : "l"(p));
}
__device__ __forceinline__ void fma2(unsigned long long& d,
                                     unsigned long long a,
                                     unsigned long long b) {
    // two independent IEEE fma.rn.f32 lanes -> bitwise == scalar accumulation
    asm("fma.rn.f32x2 %0, %1, %2, %3;" : "=l"(d) : "l"(a), "l"(b), "l"(d));
}

// -------- 1) normalize rows, write transposed (coalesced via smem) --------
__global__ void __launch_bounds__(256) norm_init_kernel(const float* __restrict__ x) {
    __shared__ float sh[DIM][33];
    if (blockIdx.x == 0 && threadIdx.x == 0) g_ecount = 0;

    int p0 = blockIdx.x * 32;
    int warp = threadIdx.x >> 5;
    int lane = threadIdx.x & 31;

    #pragma unroll
    for (int q = 0; q < 4; q++) {
        int p = p0 + warp * 4 + q;
        float a = 0.f, b = 0.f;
        if (p < N_PTS) {
            a = x[p * DIM + lane];
            b = x[p * DIM + 32 + lane];
        }
        float ss = a * a + b * b;
        #pragma unroll
        for (int o = 16; o; o >>= 1) ss += __shfl_xor_sync(0xffffffffu, ss, o);
        float s = sqrtf(ss);
        sh[lane][warp * 4 + q]      = (p < N_PTS) ? a / s : 0.f;
        sh[lane + 32][warp * 4 + q] = (p < N_PTS) ? b / s : 0.f;
    }
    __syncthreads();

    int pl = threadIdx.x & 31;
    int d0 = threadIdx.x >> 5;
    if (p0 + pl < N_PTS) {
        #pragma unroll
        for (int dd = 0; dd < DIM; dd += 8)
            g_nf_T[(d0 + dd) * N_PTS + p0 + pl] = sh[d0 + dd][pl];
    }
}

// -------- 2) 128x128 tile pairwise similarity -> edge list (FFMA2) ---------
// A tile pre-duplicated in smem as (a,a) float2 pairs: inner loop is
// 6x LDS.128 + 32 FFMA2 per k-step with ZERO pack movs -> FFMA2-pipe bound.
// Triangular 1D grid: no dead blocks.
__global__ void __launch_bounds__(256) pair_edges_kernel() {
    // decode linear block -> (bi, bj), bi <= bj, row-major over bi
    int L = blockIdx.x;
    float fb = (float)NB + 0.5f - sqrtf(((float)NB + 0.5f) * ((float)NB + 0.5f) - 2.0f * (float)L);
    int bi = (int)fb;
    if (bi > NB - 1) bi = NB - 1;
    // S(bi) = bi*NB - bi*(bi-1)/2 ; fix up (bounded correction)
    while (bi > 0 && bi * NB - bi * (bi - 1) / 2 > L) bi--;
    while ((bi + 1) * NB - (bi + 1) * bi / 2 <= L) bi++;
    int bj = bi + (L - (bi * NB - bi * (bi - 1) / 2));

    extern __shared__ float smem[];
    float2* As2 = (float2*)smem;                 // [64][128] dup pairs, 64 KB
    float*  Bs  = smem + 2 * DIM * BM;           // [64][128], 32 KB

    int t = threadIdx.x;
    int i0 = bi * BM;
    int j0 = bj * BM;

    #pragma unroll
    for (int it = 0; it < (DIM * BM) / 256; it++) {
        int idx = it * 256 + t;
        int k = idx >> 7;
        int m = idx & 127;
        float av = (i0 + m < N_PTS) ? g_nf_T[k * N_PTS + i0 + m] : 0.0f;
        As2[idx] = make_float2(av, av);
        Bs[idx]  = (j0 + m < N_PTS) ? g_nf_T[k * N_PTS + j0 + m] : 0.0f;
    }
    __syncthreads();

    int ty = t >> 4;   // 0..15 -> rows ty*4..+3 and +64
    int tx = t & 15;   // 0..15 -> cols tx*4..+3 and +64

    // acc2[r][cp]: row r (0..7), column-pair cp -> cols tx*4+(cp&1)*2+(cp>>1)*64 (+0,+1)
    unsigned long long acc2[8][4];
    #pragma unroll
    for (int r = 0; r < 8; r++)
        #pragma unroll
        for (int c = 0; c < 4; c++) acc2[r][c] = 0ull;

    #pragma unroll 8
    for (int k = 0; k < DIM; k++) {
        const ulonglong2* ak = (const ulonglong2*)(As2 + k * BM);  // 64 ull2/row
        const ulonglong2* bk = (const ulonglong2*)(Bs + k * BM);   // 32 ull2/row

        ulonglong2 a01 = ak[ty * 2];        // dup(row ty*4), dup(ty*4+1)
        ulonglong2 a23 = ak[ty * 2 + 1];    // dup(ty*4+2), dup(ty*4+3)
        ulonglong2 a45 = ak[ty * 2 + 32];   // dup(ty*4+64), dup(+65)
        ulonglong2 a67 = ak[ty * 2 + 33];
        ulonglong2 b01 = bk[tx];            // (cols 4tx,4tx+1), (4tx+2,4tx+3)
        ulonglong2 b23 = bk[tx + 16];       // (+64,+65), (+66,+67)

        unsigned long long av[8] = {a01.x, a01.y, a23.x, a23.y,
                                    a45.x, a45.y, a67.x, a67.y};
        unsigned long long bp[4] = {b01.x, b01.y, b23.x, b23.y};
        #pragma unroll
        for (int r = 0; r < 8; r++)
            #pragma unroll
            for (int c = 0; c < 4; c++)
                fma2(acc2[r][c], av[r], bp[c]);
    }

    // emit edges (sparse: mean degree ~5)
    #pragma unroll
    for (int r = 0; r < 8; r++) {
        int gi = i0 + ty * 4 + (r & 3) + (r >> 2) * 64;
        #pragma unroll
        for (int cp = 0; cp < 4; cp++) {
            float v0, v1;
            unpack2(acc2[r][cp], v0, v1);
            int gj0 = j0 + tx * 4 + ((cp & 1) * 2) + ((cp >> 1) * 64);
            if (gj0 > gi && gj0 < N_PTS && gi < N_PTS && v0 > EPS) {
                int slot = atomicAdd(&g_ecount, 1);
                if (slot < ECAP) g_edges[slot] = make_int2(gi, gj0);
            }
            int gj1 = gj0 + 1;
            if (gj1 > gi && gj1 < N_PTS && gi < N_PTS && v1 > EPS) {
                int slot = atomicAdd(&g_ecount, 1);
                if (slot < ECAP) g_edges[slot] = make_int2(gi, gj1);
            }
        }
    }
}

// -------- 3) fused CC + dense re-rank + float output (single block) --------
__global__ void __launch_bounds__(1024) cc_kernel(float* __restrict__ out) {
    extern __shared__ int dyn[];
    int* lab = dyn;               // [N_PTS]
    int* se  = dyn + N_PTS;       // [SM_EDGES] packed (u<<14 | v)
    __shared__ unsigned bitmap[WORDS];
    __shared__ int wpref[WORDS];
    __shared__ int changed;

    int t = threadIdx.x;
    for (int i = t; i < N_PTS; i += 1024) lab[i] = i;
    int m = g_ecount;
    if (m > ECAP) m = ECAP;
    int ms = m < SM_EDGES ? m : SM_EDGES;
    for (int e = t; e < ms; e += 1024) {
        int2 ed = g_edges[e];
        se[e] = (ed.x << 14) | ed.y;
    }
    __syncthreads();

    for (int iter = 0; iter < 64; iter++) {
        if (t == 0) changed = 0;
        __syncthreads();

        for (int e = t; e < ms; e += 1024) {
            int p = se[e];
            int u = p >> 14;
            int v = p & 16383;
            int a = lab[u];
            int b = lab[v];
            if (a < b) {
                if (atomicMin(&lab[v], a) > a) changed = 1;
            } else if (b < a) {
                if (atomicMin(&lab[u], b) > b) changed = 1;
            }
        }
        for (int e = SM_EDGES + t; e < m; e += 1024) {   // overflow tail
            int2 ed = g_edges[e];
            int a = lab[ed.x];
            int b = lab[ed.y];
            if (a < b) {
                if (atomicMin(&lab[ed.y], a) > a) changed = 1;
            } else if (b < a) {
                if (atomicMin(&lab[ed.x], b) > b) changed = 1;
            }
        }
        __syncthreads();

        // three pointer-jump rounds (monotone; cheap, fewer outer iters)
        #pragma unroll
        for (int j = 0; j < 3; j++) {
            for (int i = t; i < N_PTS; i += 1024) {
                int l = lab[i];
                int l2 = lab[l];
                if (l2 < l) { lab[i] = l2; changed = 1; }
            }
            __syncthreads();
        }

        int c = changed;
        __syncthreads();
        if (!c) break;
    }

    for (int w = t; w < WORDS; w += 1024) bitmap[w] = 0u;
    __syncthreads();
    for (int i = t; i < N_PTS; i += 1024)
        if (lab[i] == i) atomicOr(&bitmap[i >> 5], 1u << (i & 31));
    __syncthreads();

    if (t == 0) {
        int s = 0;
        for (int w = 0; w < WORDS; w++) { wpref[w] = s; s += __popc(bitmap[w]); }
    }
    __syncthreads();

    for (int i = t; i < N_PTS; i += 1024) {
        int l = lab[i];
        int rank = wpref[l >> 5] + __popc(bitmap[l >> 5] & ((1u << (l & 31)) - 1u));
        out[i] = (float)rank;
    }
}

extern "C" void kernel_launch(void* const* d_in, const int* in_sizes, int n_in,
                              void* d_out, int out_size) {
    const float* x = (const float*)d_in[0];
    float* out = (float*)d_out;

    const int pair_smem = 3 * DIM * BM * sizeof(float);            // 96 KB
    const int cc_smem   = (N_PTS + SM_EDGES) * sizeof(int);        // ~167 KB
    cudaFuncSetAttribute(pair_edges_kernel,
                         cudaFuncAttributeMaxDynamicSharedMemorySize, pair_smem);
    cudaFuncSetAttribute(cc_kernel,
                         cudaFuncAttributeMaxDynamicSharedMemorySize, cc_smem);

    norm_init_kernel<<<(N_PTS + 31) / 32, 256>>>(x);

    pair_edges_kernel<<<NTRI, 256, pair_smem>>>();

    cc_kernel<<<1, 1024, cc_smem>>>(out);
}

// round 9
// speedup vs baseline: 1.1863x; 1.1863x over previous
#include <cuda_runtime.h>
#include <cuda_bf16.h>

#define N_PTS 10000
#define DIM 64
#define EPS 0.4f
#define BM 128
#define NB ((N_PTS + BM - 1) / BM)       // 79
#define NTRI (NB * (NB + 1) / 2)          // 3160 upper-triangle blocks
#define ECAP (1 << 22)                    // 4M edge capacity (expect ~27K)
#define SM_EDGES 32768                    // edges cached in cc smem
#define WORDS ((N_PTS + 31) / 32)         // 313

// -------- static device scratch (no allocations allowed) --------
__device__ float g_nf_T[DIM * N_PTS];  // normalized features, TRANSPOSED [d][p]
__device__ int   g_ecount;             // edge counter
__device__ int2  g_edges[ECAP];        // edge list (u < v)

// -------- packed f32x2 helpers --------
__device__ __forceinline__ unsigned long long pack2(float lo, float hi) {
    unsigned long long r;
    asm("mov.b64 %0, {%1, %2};" : "=l"(r) : "f"(lo), "f"(hi));
    return r;
}
__device__ __forceinline__ void unpack2(unsigned long long p, float& lo, float& hi) {
    asm("mov.b64 {%0, %1}, %2;" : "=f"(lo), "=f"(hi) : "l"(p));
}
__device__ __forceinline__ void fma2(unsigned long long& d,
                                     unsigned long long a,
                                     unsigned long long b) {
    // two independent IEEE fma.rn.f32 lanes -> bitwise == scalar accumulation
    asm("fma.rn.f32x2 %0, %1, %2, %3;" : "=l"(d) : "l"(a), "l"(b), "l"(d));
}

// -------- 1) normalize rows, write transposed (coalesced via smem) --------
__global__ void __launch_bounds__(256) norm_init_kernel(const float* __restrict__ x) {
    __shared__ float sh[DIM][33];
    if (blockIdx.x == 0 && threadIdx.x == 0) g_ecount = 0;

    int p0 = blockIdx.x * 32;
    int warp = threadIdx.x >> 5;
    int lane = threadIdx.x & 31;

    #pragma unroll
    for (int q = 0; q < 4; q++) {
        int p = p0 + warp * 4 + q;
        float a = 0.f, b = 0.f;
        if (p < N_PTS) {
            a = x[p * DIM + lane];
            b = x[p * DIM + 32 + lane];
        }
        float ss = a * a + b * b;
        #pragma unroll
        for (int o = 16; o; o >>= 1) ss += __shfl_xor_sync(0xffffffffu, ss, o);
        float s = sqrtf(ss);
        sh[lane][warp * 4 + q]      = (p < N_PTS) ? a / s : 0.f;
        sh[lane + 32][warp * 4 + q] = (p < N_PTS) ? b / s : 0.f;
    }
    __syncthreads();

    int pl = threadIdx.x & 31;
    int d0 = threadIdx.x >> 5;
    if (p0 + pl < N_PTS) {
        #pragma unroll
        for (int dd = 0; dd < DIM; dd += 8)
            g_nf_T[(d0 + dd) * N_PTS + p0 + pl] = sh[d0 + dd][pl];
    }
}

// -------- 2) 128x128 tile pairwise similarity -> edge list (FFMA2) ---------
// R7-proven inner loop (4x LDS.128 + packs + 32 FFMA2 per k-step).
// New: float4-vectorized tile loads + triangular 1D grid (no dead blocks).
__global__ void __launch_bounds__(256) pair_edges_kernel() {
    // decode linear block -> (bi, bj), bi <= bj
    int L = blockIdx.x;
    float fb = (float)NB + 0.5f
             - sqrtf(((float)NB + 0.5f) * ((float)NB + 0.5f) - 2.0f * (float)L);
    int bi = (int)fb;
    if (bi > NB - 1) bi = NB - 1;
    if (bi < 0) bi = 0;
    while (bi > 0 && bi * NB - bi * (bi - 1) / 2 > L) bi--;
    while ((bi + 1) * NB - (bi + 1) * bi / 2 <= L) bi++;
    int bj = bi + (L - (bi * NB - bi * (bi - 1) / 2));

    extern __shared__ float smem[];
    float* As = smem;               // [64][128] k-major
    float* Bs = smem + DIM * BM;    // [64][128]

    int t = threadIdx.x;
    int i0 = bi * BM;
    int j0 = bj * BM;

    // ---- tile loads: float4 fast path (rows 16B-aligned: 10000 % 4 == 0) ----
    {
        float* dst = As;
        int p0 = i0;
        #pragma unroll
        for (int s = 0; s < 2; s++) {
            if (p0 + BM <= N_PTS) {
                #pragma unroll
                for (int it = 0; it < 8; it++) {
                    int idx = it * 256 + t;        // float4 index, 2048 total
                    int k = idx >> 5;              // 32 float4 per row
                    int m = idx & 31;
                    ((float4*)dst)[idx] =
                        *(const float4*)(g_nf_T + k * N_PTS + p0 + m * 4);
                }
            } else {
                #pragma unroll
                for (int it = 0; it < (DIM * BM) / 256; it++) {
                    int idx = it * 256 + t;
                    int k = idx >> 7;
                    int m = idx & 127;
                    dst[idx] = (p0 + m < N_PTS) ? g_nf_T[k * N_PTS + p0 + m] : 0.0f;
                }
            }
            dst = Bs;
            p0 = j0;
        }
    }
    __syncthreads();

    int ty = t >> 4;   // 0..15 -> rows ty*4..+3 and +64
    int tx = t & 15;   // 0..15 -> cols tx*4..+3 and +64

    unsigned long long acc2[8][4];
    #pragma unroll
    for (int r = 0; r < 8; r++)
        #pragma unroll
        for (int c = 0; c < 4; c++) acc2[r][c] = 0ull;

    #pragma unroll 8
    for (int k = 0; k < DIM; k++) {
        const float* ak = As + k * BM;
        const float* bk = Bs + k * BM;
        float4 a0 = *(const float4*)(ak + ty * 4);
        float4 a1 = *(const float4*)(ak + ty * 4 + 64);
        float4 b0 = *(const float4*)(bk + tx * 4);
        float4 b1 = *(const float4*)(bk + tx * 4 + 64);

        unsigned long long bp[4] = {
            pack2(b0.x, b0.y), pack2(b0.z, b0.w),
            pack2(b1.x, b1.y), pack2(b1.z, b1.w)
        };
        float av[8] = {a0.x, a0.y, a0.z, a0.w, a1.x, a1.y, a1.z, a1.w};
        #pragma unroll
        for (int r = 0; r < 8; r++) {
            unsigned long long ad = pack2(av[r], av[r]);
            #pragma unroll
            for (int c = 0; c < 4; c++)
                fma2(acc2[r][c], ad, bp[c]);
        }
    }

    // emit edges (sparse: mean degree ~5)
    #pragma unroll
    for (int r = 0; r < 8; r++) {
        int gi = i0 + ty * 4 + (r & 3) + (r >> 2) * 64;
        #pragma unroll
        for (int cp = 0; cp < 4; cp++) {
            float v0, v1;
            unpack2(acc2[r][cp], v0, v1);
            int gj0 = j0 + tx * 4 + ((cp & 1) * 2) + ((cp >> 1) * 64);
            if (gj0 > gi && gj0 < N_PTS && gi < N_PTS && v0 > EPS) {
                int slot = atomicAdd(&g_ecount, 1);
                if (slot < ECAP) g_edges[slot] = make_int2(gi, gj0);
            }
            int gj1 = gj0 + 1;
            if (gj1 > gi && gj1 < N_PTS && gi < N_PTS && v1 > EPS) {
                int slot = atomicAdd(&g_ecount, 1);
                if (slot < ECAP) g_edges[slot] = make_int2(gi, gj1);
            }
        }
    }
}

// -------- 3) fused CC + dense re-rank + float output (single block) --------
__global__ void __launch_bounds__(1024) cc_kernel(float* __restrict__ out) {
    extern __shared__ int dyn[];
    int* lab = dyn;               // [N_PTS]
    int* se  = dyn + N_PTS;       // [SM_EDGES] packed (u<<14 | v)
    __shared__ unsigned bitmap[WORDS];
    __shared__ int wpref[WORDS];
    __shared__ int changed;

    int t = threadIdx.x;
    for (int i = t; i < N_PTS; i += 1024) lab[i] = i;
    int m = g_ecount;
    if (m > ECAP) m = ECAP;
    int ms = m < SM_EDGES ? m : SM_EDGES;
    for (int e = t; e < ms; e += 1024) {
        int2 ed = g_edges[e];
        se[e] = (ed.x << 14) | ed.y;
    }
    __syncthreads();

    for (int iter = 0; iter < 64; iter++) {
        if (t == 0) changed = 0;
        __syncthreads();

        for (int e = t; e < ms; e += 1024) {
            int p = se[e];
            int u = p >> 14;
            int v = p & 16383;
            int a = lab[u];
            int b = lab[v];
            if (a < b) {
                if (atomicMin(&lab[v], a) > a) changed = 1;
            } else if (b < a) {
                if (atomicMin(&lab[u], b) > b) changed = 1;
            }
        }
        for (int e = SM_EDGES + t; e < m; e += 1024) {   // overflow tail
            int2 ed = g_edges[e];
            int a = lab[ed.x];
            int b = lab[ed.y];
            if (a < b) {
                if (atomicMin(&lab[ed.y], a) > a) changed = 1;
            } else if (b < a) {
                if (atomicMin(&lab[ed.x], b) > b) changed = 1;
            }
        }
        __syncthreads();

        #pragma unroll
        for (int j = 0; j < 3; j++) {
            for (int i = t; i < N_PTS; i += 1024) {
                int l = lab[i];
                int l2 = lab[l];
                if (l2 < l) { lab[i] = l2; changed = 1; }
            }
            __syncthreads();
        }

        int c = changed;
        __syncthreads();
        if (!c) break;
    }

    for (int w = t; w < WORDS; w += 1024) bitmap[w] = 0u;
    __syncthreads();
    for (int i = t; i < N_PTS; i += 1024)
        if (lab[i] == i) atomicOr(&bitmap[i >> 5], 1u << (i & 31));
    __syncthreads();

    if (t == 0) {
        int s = 0;
        for (int w = 0; w < WORDS; w++) { wpref[w] = s; s += __popc(bitmap[w]); }
    }
    __syncthreads();

    for (int i = t; i < N_PTS; i += 1024) {
        int l = lab[i];
        int rank = wpref[l >> 5] + __popc(bitmap[l >> 5] & ((1u << (l & 31)) - 1u));
        out[i] = (float)rank;
    }
}

extern "C" void kernel_launch(void* const* d_in, const int* in_sizes, int n_in,
                              void* d_out, int out_size) {
    const float* x = (const float*)d_in[0];
    float* out = (float*)d_out;

    const int pair_smem = 2 * DIM * BM * sizeof(float);            // 64 KB
    const int cc_smem   = (N_PTS + SM_EDGES) * sizeof(int);        // ~167 KB
    cudaFuncSetAttribute(pair_edges_kernel,
                         cudaFuncAttributeMaxDynamicSharedMemorySize, pair_smem);
    cudaFuncSetAttribute(cc_kernel,
                         cudaFuncAttributeMaxDynamicSharedMemorySize, cc_smem);

    norm_init_kernel<<<(N_PTS + 31) / 32, 256>>>(x);

    pair_edges_kernel<<<NTRI, 256, pair_smem>>>();

    cc_kernel<<<1, 1024, cc_smem>>>(out);
}